// round 2
// baseline (speedup 1.0000x reference)
#include <cuda_runtime.h>
#include <cstddef>

// ManyBodyVoxel: out[0, a, c=t*2+l, x, y, z] =
//   sum_n exp(coeff * || grid_l[x,y,z] - d[a,n]*mask_t[a,n] ||^2)
// Separable Gaussian: rank-1 outer products from per-(atom,axis,tick) exp tables.
// Non-matching atoms contribute the d=0 base Gaussian (mask zeroes d, doesn't drop terms).
// R2: one CTA per (a, l, t) -> grid=1280, short critical path, low regs, high occupancy.

#define NTHREADS 256

__global__ __launch_bounds__(NTHREADS)
void mbv_kernel(const float* __restrict__ dist,     // (1,128,64,3) fp32
                const float* __restrict__ sigma,    // (1,) fp32
                const int*   __restrict__ anum_raw, // (128,64) int32 or int64 (auto-detect)
                float* __restrict__ out)            // (1,128,10,16,16,16) fp32
{
    const int blk = blockIdx.x;        // a*10 + t*2 + l
    const int a   = blk / 10;
    const int ch  = blk - a * 10;
    const int t   = ch >> 1;
    const int l   = ch & 1;
    const float L = l ? 12.0f : 8.0f;
    const int tid = threadIdx.x;

    __shared__ __align__(16) float tab[65][3][16]; // compacted: [0..cnt) matching atoms, [cnt] = base (d=0)
    __shared__ int lst[64];
    __shared__ int cnt;
    __shared__ int is64;

    if (tid == 0) { cnt = 0; is64 = 1; }
    __syncthreads();
    // int64 vs int32 detection: int64 small values => odd 32-bit words all zero.
    if (tid < 64 && anum_raw[2 * tid + 1] != 0) atomicAnd(&is64, 0);
    __syncthreads();
    const int w64 = is64;

    const int ztarget = (t == 0) ? 1 : (t == 1) ? 6 : (t == 2) ? 7 : (t == 3) ? 8 : 16;
    if (tid < 64) {
        int z = w64 ? anum_raw[(a * 64 + tid) * 2] : anum_raw[a * 64 + tid];
        if (z == ztarget) { int idx = atomicAdd(&cnt, 1); lst[idx] = tid; }
    }
    __syncthreads();
    const int cn = cnt;

    const float s    = sigma[0];
    const float cf   = -0.5f / (s * s);
    const float half = 0.5f * L;
    const float step = L * (1.0f / 15.0f);

    // Exp tables: (cn+1) x 3 axes x 16 ticks; expected cn ~ 4 -> ~1 exp per thread.
    for (int i = tid; i < (cn + 1) * 48; i += NTHREADS) {
        int n  = i / 48;
        int r  = i - n * 48;
        int ax = r >> 4;
        int j  = r & 15;
        float dv = (n < cn) ? dist[(a * 64 + lst[n]) * 3 + ax] : 0.0f;
        float u  = (step * (float)j - half) - dv;
        tab[n][ax][j] = __expf(cf * u * u);
    }
    __syncthreads();

    const int x = tid >> 4;
    const int y = tid & 15;

    float4 a0 = make_float4(0.f, 0.f, 0.f, 0.f);
    float4 a1 = a0, a2 = a0, a3 = a0;

    for (int k = 0; k < cn; k++) {
        float sxy = tab[k][0][x] * tab[k][1][y];
        const float4* ez = reinterpret_cast<const float4*>(tab[k][2]);
        float4 e0 = ez[0], e1 = ez[1], e2 = ez[2], e3 = ez[3];
        a0.x += sxy * e0.x; a0.y += sxy * e0.y; a0.z += sxy * e0.z; a0.w += sxy * e0.w;
        a1.x += sxy * e1.x; a1.y += sxy * e1.y; a1.z += sxy * e1.z; a1.w += sxy * e1.w;
        a2.x += sxy * e2.x; a2.y += sxy * e2.y; a2.z += sxy * e2.z; a2.w += sxy * e2.w;
        a3.x += sxy * e3.x; a3.y += sxy * e3.y; a3.z += sxy * e3.z; a3.w += sxy * e3.w;
    }

    // Base contribution from the (64 - cn) non-matching atoms (d = 0).
    {
        float bm = (float)(64 - cn) * tab[cn][0][x] * tab[cn][1][y];
        const float4* bz = reinterpret_cast<const float4*>(tab[cn][2]);
        float4 b0 = bz[0], b1 = bz[1], b2 = bz[2], b3 = bz[3];
        a0.x += bm * b0.x; a0.y += bm * b0.y; a0.z += bm * b0.z; a0.w += bm * b0.w;
        a1.x += bm * b1.x; a1.y += bm * b1.y; a1.z += bm * b1.z; a1.w += bm * b1.w;
        a2.x += bm * b2.x; a2.y += bm * b2.y; a2.z += bm * b2.z; a2.w += bm * b2.w;
        a3.x += bm * b3.x; a3.y += bm * b3.y; a3.z += bm * b3.z; a3.w += bm * b3.w;
    }

    // Voxel index = x*256 + y*16 + z; channel base = (a*10 + ch) * 4096.
    size_t off = (((size_t)blk) << 12) + ((size_t)x << 8) + ((size_t)y << 4);
    float4* op = reinterpret_cast<float4*>(out + off);
    op[0] = a0; op[1] = a1; op[2] = a2; op[3] = a3;
}

extern "C" void kernel_launch(void* const* d_in, const int* in_sizes, int n_in,
                              void* d_out, int out_size) {
    const float* dist = nullptr;
    const float* sig  = nullptr;
    const int*   an   = nullptr;
    for (int i = 0; i < n_in; i++) {
        if (in_sizes[i] == 1)          sig  = (const float*)d_in[i];
        else if (in_sizes[i] == 24576) dist = (const float*)d_in[i];
        else if (in_sizes[i] == 8192)  an   = (const int*)d_in[i];
    }
    if (!dist) dist = (const float*)d_in[0];
    if (!sig)  sig  = (const float*)d_in[1];
    if (!an)   an   = (const int*)d_in[2];

    mbv_kernel<<<1280, NTHREADS>>>(dist, sig, an, (float*)d_out);
}

// round 3
// speedup vs baseline: 1.3578x; 1.3578x over previous
#include <cuda_runtime.h>
#include <cstddef>

// ManyBodyVoxel: out[0, a, c=t*2+l, x, y, z] =
//   sum_n exp(coeff * || grid_l[x,y,z] - d[a,n]*mask_t[a,n] ||^2)
// Separable Gaussian -> rank-1 outer products of per-(atom,axis) exp rows.
// Non-matching atoms contribute the d=0 base Gaussian (mask zeroes d, doesn't drop terms).
// R3: 128 CTAs (one per a) x 512 threads (l = tid>>8), single wave, ONE barrier,
//     warp0 classifies while other warps build exp tables, pipelined consumer.

#define NT 512

__global__ __launch_bounds__(NT, 1)
void mbv_kernel(const float* __restrict__ dist,   // (1,128,64,3) fp32
                const float* __restrict__ sigma,  // (1,) fp32
                const int*   __restrict__ anum,   // (128,64) int64 or int32 (auto-detect)
                float* __restrict__ out)          // (1,128,10,16,16,16) fp32
{
    const int a   = blockIdx.x;
    const int tid = threadIdx.x;
    const int l   = tid >> 8;        // 0: L=8, 1: L=12
    const int xy  = tid & 255;
    const int x   = xy >> 4;
    const int y   = xy & 15;

    __shared__ float tabx[2][65][16];                 // row 64 = base (d=0)
    __shared__ float taby[2][65][16];
    __shared__ __align__(16) float tabz[2][65][16];
    __shared__ int   lst[5][64];
    __shared__ int   cnt[5];

    const float s  = sigma[0];
    const float cf = -0.5f / (s * s);

    // ---- Warp 0: dtype probe + classification (no extra barriers) ----
    if (tid < 32) {
        if (tid < 5) cnt[tid] = 0;
        __syncwarp();
        // Probe row 0: int64 small values => all odd 32-bit words zero.
        // bytes [tid*16, tid*16+16) <= 512 — in-bounds for either dtype.
        int4 p = ((const int4*)anum)[tid];
        bool i32 = __any_sync(0xffffffffu, (p.y | p.w) != 0);
        // Entries 2*tid and 2*tid+1 of row a.
        int z0, z1;
        if (!i32) {
            int4 q = ((const int4*)anum)[a * 32 + tid];   // int64 row = 512B
            z0 = q.x; z1 = q.z;
        } else {
            int2 q = ((const int2*)anum)[a * 32 + tid];   // int32 row = 256B
            z0 = q.x; z1 = q.y;
        }
        #pragma unroll
        for (int e = 0; e < 2; e++) {
            int z = e ? z1 : z0;
            int n = 2 * tid + e;
            int t = (z == 1) ? 0 : (z == 6) ? 1 : (z == 7) ? 2 : (z == 8) ? 3 : (z == 16) ? 4 : -1;
            if (t >= 0) { int idx = atomicAdd(&cnt[t], 1); lst[t][idx] = n; }
        }
    }

    // ---- Warps 1..15: exp tables (independent of classification) ----
    // Unit u in [0, 390): l' = u/195, r = u%195, n = r/3, ax = r%3; 16 exps each.
    {
        int u = tid - 32;
        if (u >= 0 && u < 390) {
            int lp = (u >= 195) ? 1 : 0;
            int r  = u - lp * 195;
            int n  = r / 3;
            int ax = r - n * 3;
            float Lp   = lp ? 12.0f : 8.0f;
            float half = 0.5f * Lp;
            float step = Lp * (1.0f / 15.0f);
            float dv   = (n < 64) ? __ldg(&dist[(a * 64 + n) * 3 + ax]) : 0.0f;
            float* dst = (ax == 0 ? tabx[lp][n] : ax == 1 ? taby[lp][n] : tabz[lp][n]);
            float base = -half - dv;
            #pragma unroll
            for (int j = 0; j < 16; j++) {
                float uu = base + step * (float)j;
                dst[j] = __expf(cf * uu * uu);
            }
        }
    }

    __syncthreads();   // the only CTA-wide barrier

    // ---- Consumer: each thread owns one (l, x, y) column of 16 z voxels ----
    const float bxy = tabx[l][64][x] * taby[l][64][y];
    const float4* bzp = reinterpret_cast<const float4*>(tabz[l][64]);
    const float4 bz0 = bzp[0], bz1 = bzp[1], bz2 = bzp[2], bz3 = bzp[3];

    #pragma unroll
    for (int t = 0; t < 5; t++) {
        const int c = cnt[t];
        const float bm = (float)(64 - c) * bxy;
        float4 a0, a1, a2, a3;
        a0.x = bm * bz0.x; a0.y = bm * bz0.y; a0.z = bm * bz0.z; a0.w = bm * bz0.w;
        a1.x = bm * bz1.x; a1.y = bm * bz1.y; a1.z = bm * bz1.z; a1.w = bm * bz1.w;
        a2.x = bm * bz2.x; a2.y = bm * bz2.y; a2.z = bm * bz2.z; a2.w = bm * bz2.w;
        a3.x = bm * bz3.x; a3.y = bm * bz3.y; a3.z = bm * bz3.z; a3.w = bm * bz3.w;

        if (c > 0) {
            // software pipeline: prefetch next atom's rows during current FMAs
            int n = lst[t][0];
            float sx = tabx[l][n][x];
            float sy = taby[l][n][y];
            const float4* zp = reinterpret_cast<const float4*>(tabz[l][n]);
            float4 e0 = zp[0], e1 = zp[1], e2 = zp[2], e3 = zp[3];
            for (int k = 0; k < c; k++) {
                float sxn = 0.f, syn = 0.f;
                float4 f0, f1, f2, f3;
                if (k + 1 < c) {
                    int np = lst[t][k + 1];
                    sxn = tabx[l][np][x];
                    syn = taby[l][np][y];
                    const float4* zq = reinterpret_cast<const float4*>(tabz[l][np]);
                    f0 = zq[0]; f1 = zq[1]; f2 = zq[2]; f3 = zq[3];
                }
                float sxy = sx * sy;
                a0.x += sxy * e0.x; a0.y += sxy * e0.y; a0.z += sxy * e0.z; a0.w += sxy * e0.w;
                a1.x += sxy * e1.x; a1.y += sxy * e1.y; a1.z += sxy * e1.z; a1.w += sxy * e1.w;
                a2.x += sxy * e2.x; a2.y += sxy * e2.y; a2.z += sxy * e2.z; a2.w += sxy * e2.w;
                a3.x += sxy * e3.x; a3.y += sxy * e3.y; a3.z += sxy * e3.z; a3.w += sxy * e3.w;
                sx = sxn; sy = syn;
                e0 = f0; e1 = f1; e2 = f2; e3 = f3;
            }
        }

        // channel = a*10 + t*2 + l; voxel = x*256 + y*16 + z
        size_t off = (((size_t)(a * 10 + t * 2 + l)) << 12) + ((size_t)x << 8) + ((size_t)y << 4);
        float4* op = reinterpret_cast<float4*>(out + off);
        op[0] = a0; op[1] = a1; op[2] = a2; op[3] = a3;
    }
}

extern "C" void kernel_launch(void* const* d_in, const int* in_sizes, int n_in,
                              void* d_out, int out_size) {
    const float* dist = nullptr;
    const float* sig  = nullptr;
    const int*   an   = nullptr;
    for (int i = 0; i < n_in; i++) {
        if (in_sizes[i] == 1)          sig  = (const float*)d_in[i];
        else if (in_sizes[i] == 24576) dist = (const float*)d_in[i];
        else if (in_sizes[i] == 8192)  an   = (const int*)d_in[i];
    }
    if (!dist) dist = (const float*)d_in[0];
    if (!sig)  sig  = (const float*)d_in[1];
    if (!an)   an   = (const int*)d_in[2];

    mbv_kernel<<<128, NT>>>(dist, sig, an, (float*)d_out);
}

// round 4
// speedup vs baseline: 1.5012x; 1.1057x over previous
#include <cuda_runtime.h>
#include <cstddef>

// ManyBodyVoxel: out[0, a, c=t*2+l, x, y, z] =
//   sum_n exp(coeff * || grid_l[x,y,z] - d[a,n]*mask_t[a,n] ||^2)
// Separable Gaussian -> rank-1 outer products of per-(atom,axis) exp rows.
// Non-matching atoms contribute the d=0 base Gaussian.
// R4: 128 CTAs x 1024 threads (thread = (l, x, y, zhalf) owning 8 voxels),
//     occ ~46%, packed f32x2 FMAs in the hot loop, one barrier.

#define NT 1024

__device__ __forceinline__ unsigned long long pk2(float lo, float hi) {
    unsigned long long r;
    asm("mov.b64 %0, {%1, %2};" : "=l"(r) : "f"(lo), "f"(hi));
    return r;
}
__device__ __forceinline__ unsigned long long fma2(unsigned long long a,
                                                   unsigned long long b,
                                                   unsigned long long c) {
    unsigned long long d;
    asm("fma.rn.f32x2 %0, %1, %2, %3;" : "=l"(d) : "l"(a), "l"(b), "l"(c));
    return d;
}
__device__ __forceinline__ unsigned long long mul2(unsigned long long a,
                                                   unsigned long long b) {
    unsigned long long d;
    asm("mul.rn.f32x2 %0, %1, %2;" : "=l"(d) : "l"(a), "l"(b));
    return d;
}

__global__ __launch_bounds__(NT, 1)
void mbv_kernel(const float* __restrict__ dist,   // (1,128,64,3) fp32
                const float* __restrict__ sigma,  // (1,) fp32
                const int*   __restrict__ anum,   // (128,64) int64 or int32 (auto-detect)
                float* __restrict__ out)          // (1,128,10,16,16,16) fp32
{
    const int a   = blockIdx.x;
    const int tid = threadIdx.x;
    // zh fastest for coalesced stores: zh = bit0, y = bits1-4, x = bits5-8, l = bit9
    const int zh  = tid & 1;
    const int y   = (tid >> 1) & 15;
    const int x   = (tid >> 5) & 15;
    const int l   = tid >> 9;

    __shared__ float tabx[2][65][16];                 // row 64 = base (d=0)
    __shared__ float taby[2][65][16];
    __shared__ __align__(16) float tabz[2][65][16];
    __shared__ int   lst[5][64];
    __shared__ int   cnt[5];

    const float s  = sigma[0];
    const float cf = -0.5f / (s * s);

    // ---- Warp 0: dtype probe + classification ----
    if (tid < 32) {
        if (tid < 5) cnt[tid] = 0;
        __syncwarp();
        // Probe row 0: int64 small values => odd 32-bit words all zero.
        int4 p = ((const int4*)anum)[tid];
        bool i32 = __any_sync(0xffffffffu, (p.y | p.w) != 0);
        int z0, z1;
        if (!i32) {
            int4 q = ((const int4*)anum)[a * 32 + tid];   // int64 row = 512B
            z0 = q.x; z1 = q.z;
        } else {
            int2 q = ((const int2*)anum)[a * 32 + tid];   // int32 row = 256B
            z0 = q.x; z1 = q.y;
        }
        #pragma unroll
        for (int e = 0; e < 2; e++) {
            int z = e ? z1 : z0;
            int n = 2 * tid + e;
            int t = (z == 1) ? 0 : (z == 6) ? 1 : (z == 7) ? 2 : (z == 8) ? 3 : (z == 16) ? 4 : -1;
            if (t >= 0) { int idx = atomicAdd(&cnt[t], 1); lst[t][idx] = n; }
        }
    }

    // ---- Warps 1..31: exp tables. Unit u in [0,390): lp=u/195, n=(u%195)/3, ax=%3 ----
    {
        int u = tid - 32;
        if (u >= 0 && u < 390) {
            int lp = (u >= 195) ? 1 : 0;
            int r  = u - lp * 195;
            int n  = r / 3;
            int ax = r - n * 3;
            float Lp   = lp ? 12.0f : 8.0f;
            float half = 0.5f * Lp;
            float step = Lp * (1.0f / 15.0f);
            float dv   = (n < 64) ? __ldg(&dist[(a * 64 + n) * 3 + ax]) : 0.0f;
            float* dst = (ax == 0 ? tabx[lp][n] : ax == 1 ? taby[lp][n] : tabz[lp][n]);
            float base = -half - dv;
            #pragma unroll
            for (int j = 0; j < 16; j++) {
                float uu = base + step * (float)j;
                dst[j] = __expf(cf * uu * uu);
            }
        }
    }

    __syncthreads();   // the only CTA-wide barrier

    // ---- Consumer: thread owns 8 voxels z in [zh*8, zh*8+8) of column (l,x,y) ----
    typedef unsigned long long u64;
    const float bxy = tabx[l][64][x] * taby[l][64][y];
    const ulonglong2* bzr = reinterpret_cast<const ulonglong2*>(&tabz[l][64][zh * 8]);
    const ulonglong2 bq0 = bzr[0], bq1 = bzr[1];   // 4 packed z-pairs

    #pragma unroll
    for (int t = 0; t < 5; t++) {
        const int c = cnt[t];
        const float bm = (float)(64 - c) * bxy;
        const u64 bmp = pk2(bm, bm);
        u64 a0 = mul2(bmp, bq0.x);
        u64 a1 = mul2(bmp, bq0.y);
        u64 a2 = mul2(bmp, bq1.x);
        u64 a3 = mul2(bmp, bq1.y);

        if (c > 0) {
            int n0 = lst[t][0];
            float sx = tabx[l][n0][x];
            float sy = taby[l][n0][y];
            const ulonglong2* zr = reinterpret_cast<const ulonglong2*>(&tabz[l][n0][zh * 8]);
            ulonglong2 q0 = zr[0], q1 = zr[1];
            for (int k = 0; k < c; k++) {
                float sxn = 0.f, syn = 0.f;
                ulonglong2 r0, r1;
                if (k + 1 < c) {
                    int np = lst[t][k + 1];
                    sxn = tabx[l][np][x];
                    syn = taby[l][np][y];
                    const ulonglong2* zq = reinterpret_cast<const ulonglong2*>(&tabz[l][np][zh * 8]);
                    r0 = zq[0]; r1 = zq[1];
                }
                float sxy = sx * sy;
                u64 sp = pk2(sxy, sxy);
                a0 = fma2(sp, q0.x, a0);
                a1 = fma2(sp, q0.y, a1);
                a2 = fma2(sp, q1.x, a2);
                a3 = fma2(sp, q1.y, a3);
                sx = sxn; sy = syn; q0 = r0; q1 = r1;
            }
        }

        // channel = a*10 + t*2 + l; voxel = x*256 + y*16 + zh*8
        size_t off = (((size_t)(a * 10 + t * 2 + l)) << 12)
                   + ((size_t)x << 8) + ((size_t)y << 4) + ((size_t)zh << 3);
        ulonglong2* op = reinterpret_cast<ulonglong2*>(out + off);
        op[0] = make_ulonglong2(a0, a1);
        op[1] = make_ulonglong2(a2, a3);
    }
}

extern "C" void kernel_launch(void* const* d_in, const int* in_sizes, int n_in,
                              void* d_out, int out_size) {
    const float* dist = nullptr;
    const float* sig  = nullptr;
    const int*   an   = nullptr;
    for (int i = 0; i < n_in; i++) {
        if (in_sizes[i] == 1)          sig  = (const float*)d_in[i];
        else if (in_sizes[i] == 24576) dist = (const float*)d_in[i];
        else if (in_sizes[i] == 8192)  an   = (const int*)d_in[i];
    }
    if (!dist) dist = (const float*)d_in[0];
    if (!sig)  sig  = (const float*)d_in[1];
    if (!an)   an   = (const int*)d_in[2];

    mbv_kernel<<<128, NT>>>(dist, sig, an, (float*)d_out);
}

// round 5
// speedup vs baseline: 1.5313x; 1.0201x over previous
#include <cuda_runtime.h>
#include <cstddef>

// ManyBodyVoxel: out[0, a, c=t*2+l, x, y, z] =
//   sum_n exp(coeff * || grid_l[x,y,z] - d[a,n]*mask_t[a,n] ||^2)
// Separable Gaussian -> rank-1 outer products of per-(atom,axis) exp rows.
// Non-matching atoms contribute the d=0 base Gaussian.
// R5: ballot-compacted classification (no atomics, single L2 round trip),
//     contiguous 256B per-(l,atom) table records, byte-offset atom lists,
//     packed f32x2 FMAs, streaming stores.

#define NT 1024

typedef unsigned long long u64;

__device__ __forceinline__ u64 pk2(float v) {
    u64 r; asm("mov.b64 %0, {%1, %2};" : "=l"(r) : "f"(v), "f"(v)); return r;
}
__device__ __forceinline__ u64 fma2(u64 a, u64 b, u64 c) {
    u64 d; asm("fma.rn.f32x2 %0, %1, %2, %3;" : "=l"(d) : "l"(a), "l"(b), "l"(c)); return d;
}
__device__ __forceinline__ u64 mul2(u64 a, u64 b) {
    u64 d; asm("mul.rn.f32x2 %0, %1, %2;" : "=l"(d) : "l"(a), "l"(b)); return d;
}

__global__ __launch_bounds__(NT, 1)
void mbv_kernel(const float* __restrict__ dist,   // (1,128,64,3) fp32
                const float* __restrict__ sigma,  // (1,) fp32
                const int*   __restrict__ anum,   // (128,64) int64 or int32 (auto-detect)
                float* __restrict__ out)          // (1,128,10,16,16,16) fp32
{
    const int a   = blockIdx.x;
    const int tid = threadIdx.x;
    const int zh  = tid & 1;          // z half: [zh*8, zh*8+8)
    const int y   = (tid >> 1) & 15;
    const int x   = (tid >> 5) & 15;
    const int l   = tid >> 9;         // 0: L=8, 1: L=12

    // Record (l,n): 64 floats = 256B.  x @ +0, y @ +64B, z @ +128B, pad @ +192B.
    __shared__ __align__(16) float tab[2 * 65 * 64];
    __shared__ int lst[5][64];        // premultiplied byte offsets (n*256)
    __shared__ int cnt[5];

    const float s  = sigma[0];
    const float cf = -0.5f / (s * s);

    // ---- Warp 0: probe + classify, ballot compaction, zero atomics ----
    if (tid < 32) {
        // Three independent LDGs in flight (one L2 round trip total).
        int4 p = ((const int4*)anum)[tid];            // probe row 0
        int4 q = ((const int4*)anum)[a * 32 + tid];   // int64 interpretation
        int2 r = ((const int2*)anum)[a * 32 + tid];   // int32 interpretation
        bool i32 = __any_sync(0xffffffffu, (p.y | p.w) != 0);
        int z0 = i32 ? r.x : q.x;     // atom 2*tid
        int z1 = i32 ? r.y : q.z;     // atom 2*tid+1
        unsigned lt = (1u << tid) - 1u;   // lanemask_lt (tid<32 here)
        const int ZT[5] = {1, 6, 7, 8, 16};
        #pragma unroll
        for (int t = 0; t < 5; t++) {
            unsigned m0 = __ballot_sync(0xffffffffu, z0 == ZT[t]);
            unsigned m1 = __ballot_sync(0xffffffffu, z1 == ZT[t]);
            if (z0 == ZT[t]) lst[t][__popc(m0 & lt)]              = (2 * tid)     * 256;
            if (z1 == ZT[t]) lst[t][__popc(m0) + __popc(m1 & lt)] = (2 * tid + 1) * 256;
            if (tid == 0)    cnt[t] = __popc(m0) + __popc(m1);
        }
    }

    // ---- Threads 64..453: exp tables (independent of classification) ----
    {
        int u = tid - 64;
        if (u >= 0 && u < 390) {
            int lp = (u >= 195) ? 1 : 0;
            int rr = u - lp * 195;
            int n  = rr / 3;
            int ax = rr - n * 3;      // 0:x 1:y 2:z
            float Lp   = lp ? 12.0f : 8.0f;
            float half = 0.5f * Lp;
            float step = Lp * (1.0f / 15.0f);
            float dv   = (n < 64) ? __ldg(&dist[(a * 64 + n) * 3 + ax]) : 0.0f;
            float* dst = &tab[(lp * 65 + n) * 64 + ax * 16];
            float base = -half - dv;
            #pragma unroll
            for (int j = 0; j < 16; j++) {
                float uu = base + step * (float)j;
                dst[j] = __expf(cf * uu * uu);
            }
        }
    }

    __syncthreads();   // the only CTA-wide barrier

    // ---- Consumer ----
    const char* tb = reinterpret_cast<const char*>(tab) + l * (65 * 256);
    const int offx = x * 4;            // byte offsets within a record
    const int offy = 64 + y * 4;
    const int offz = 128 + zh * 32;

    // Base record (n = 64).
    const char* br = tb + 64 * 256;
    const float bxy = *(const float*)(br + offx) * *(const float*)(br + offy);
    const ulonglong2 bqa = *(const ulonglong2*)(br + offz);        // z[zh*8..+3]
    const ulonglong2 bqb = *(const ulonglong2*)(br + offz + 16);   // z[zh*8+4..+7]
    const u64 Pxy = pk2(bxy);
    const u64 B0 = mul2(Pxy, bqa.x), B1 = mul2(Pxy, bqa.y);
    const u64 B2 = mul2(Pxy, bqb.x), B3 = mul2(Pxy, bqb.y);

    // Store base: channel = a*10 + t*2 + l, voxel = x*256 + y*16 + zh*8.
    char* op = reinterpret_cast<char*>(out)
             + ((((size_t)(a * 10 + l)) << 12) + ((size_t)x << 8) + ((size_t)y << 4) + ((size_t)zh << 3)) * 4;

    #pragma unroll
    for (int t = 0; t < 5; t++) {
        const int c = cnt[t];
        const u64 bm = pk2((float)(64 - c));
        u64 a0 = mul2(bm, B0), a1 = mul2(bm, B1), a2 = mul2(bm, B2), a3 = mul2(bm, B3);

        if (c > 0) {
            const char* rec = tb + lst[t][0];
            float sx = *(const float*)(rec + offx);
            float sy = *(const float*)(rec + offy);
            ulonglong2 qa = *(const ulonglong2*)(rec + offz);
            ulonglong2 qb = *(const ulonglong2*)(rec + offz + 16);
            for (int k = 0; k < c; k++) {
                float sxn = 0.f, syn = 0.f;
                ulonglong2 ra, rb;
                if (k + 1 < c) {   // prefetch next atom's rows under current FMAs
                    const char* rn = tb + lst[t][k + 1];
                    sxn = *(const float*)(rn + offx);
                    syn = *(const float*)(rn + offy);
                    ra  = *(const ulonglong2*)(rn + offz);
                    rb  = *(const ulonglong2*)(rn + offz + 16);
                }
                u64 sp = pk2(sx * sy);
                a0 = fma2(sp, qa.x, a0);
                a1 = fma2(sp, qa.y, a1);
                a2 = fma2(sp, qb.x, a2);
                a3 = fma2(sp, qb.y, a3);
                sx = sxn; sy = syn; qa = ra; qb = rb;
            }
        }

        // Streaming 32B store (two 16B) — keep it out of L1.
        __stcs((ulonglong2*)op,        make_ulonglong2(a0, a1));
        __stcs((ulonglong2*)(op + 16), make_ulonglong2(a2, a3));
        op += 2 * 4096 * 4;   // next type channel (t*2 stride in channels)
    }
}

extern "C" void kernel_launch(void* const* d_in, const int* in_sizes, int n_in,
                              void* d_out, int out_size) {
    const float* dist = nullptr;
    const float* sig  = nullptr;
    const int*   an   = nullptr;
    for (int i = 0; i < n_in; i++) {
        if (in_sizes[i] == 1)          sig  = (const float*)d_in[i];
        else if (in_sizes[i] == 24576) dist = (const float*)d_in[i];
        else if (in_sizes[i] == 8192)  an   = (const int*)d_in[i];
    }
    if (!dist) dist = (const float*)d_in[0];
    if (!sig)  sig  = (const float*)d_in[1];
    if (!an)   an   = (const int*)d_in[2];

    mbv_kernel<<<128, NT>>>(dist, sig, an, (float*)d_out);
}